// round 1
// baseline (speedup 1.0000x reference)
#include <cuda_runtime.h>

// ---------------------------------------------------------------------------
// GraphSAGE (2x SAGEConv mean-agg + ReLU + global mean pool), fp32.
//
// Math:
//   agg1[n] = (1/max(deg[n],1)) * sum_{e:dst=n} x[src[e]]
//   h1[n]   = relu( agg1[n] @ Wl1^T + x[n] @ Wr1^T + b1 )
//   agg2[n] = (1/max(deg[n],1)) * sum_{e:dst=n} h1[src[e]]
//   out[g]  = (sum_{n in g} agg2[n]) / max(cnt,1) @ Wl2^T
//           + (sum_{n in g} h1[n])   / max(cnt,1) @ Wr2^T
//           + b2 * [cnt > 0]
// (h2 per-node is never materialized: pooling commutes with the linear layer)
// ---------------------------------------------------------------------------

#define N_NODES 100000
#define FDIM    64
#define NGRAPHS 128
#define TILE    24   // nodes per block tile in h1 GEMM (3 per warp, 8 warps)

__device__ __align__(16) float g_agg1[(size_t)N_NODES * FDIM];
__device__ __align__(16) float g_h1  [(size_t)N_NODES * FDIM];
__device__ __align__(16) float g_agg2[(size_t)N_NODES * FDIM];
__device__ float g_deg[N_NODES];
__device__ float g_pooled[NGRAPHS * 128];   // [g][0:64]=sum h1, [g][64:128]=sum agg2
__device__ float g_cnt[NGRAPHS];
__device__ int   g_is64;

// ---------------------------------------------------------------------------
// Zero accumulators + detect index width (int64 vs int32).
// For int64 little-endian node ids (< 2^31, nonneg), every odd 32-bit word is 0.
// For int32 random ids in [0,100000), 64 consecutive zeros has prob ~1e-320.
// ---------------------------------------------------------------------------
__global__ void k_zero(const int* __restrict__ edge_w) {
    size_t stride = (size_t)gridDim.x * blockDim.x;
    size_t t0 = (size_t)blockIdx.x * blockDim.x + threadIdx.x;
    for (size_t i = t0; i < (size_t)N_NODES * FDIM; i += stride) {
        g_agg1[i] = 0.f;
        g_agg2[i] = 0.f;
    }
    for (size_t i = t0; i < (size_t)N_NODES; i += stride) g_deg[i] = 0.f;
    for (size_t i = t0; i < (size_t)NGRAPHS * 128; i += stride) g_pooled[i] = 0.f;
    for (size_t i = t0; i < (size_t)NGRAPHS; i += stride) g_cnt[i] = 0.f;

    if (blockIdx.x == 0 && threadIdx.x == 0) {
        int is64 = 1;
        #pragma unroll 1
        for (int i = 1; i < 128; i += 2) {
            if (edge_w[i] != 0) { is64 = 0; break; }
        }
        g_is64 = is64;
    }
}

// ---------------------------------------------------------------------------
// Edge scatter: 16 lanes per edge, each lane moves one float4 (64 ch total).
// phase1: feat = x,   agg = g_agg1, also counts degree.
// phase2: feat = h1,  agg = g_agg2.
// ---------------------------------------------------------------------------
__global__ void k_scatter(const float4* __restrict__ xin,
                          const void* __restrict__ edge, int E, int phase1) {
    const float4* feat = phase1 ? xin : (const float4*)g_h1;
    float* agg = phase1 ? g_agg1 : g_agg2;

    int gtid   = blockIdx.x * blockDim.x + threadIdx.x;
    int lane16 = gtid & 15;
    int group  = gtid >> 4;
    int ngroups = (gridDim.x * blockDim.x) >> 4;
    const bool is64 = (g_is64 != 0);

    for (int e = group; e < E; e += ngroups) {
        int src, dst;
        if (is64) {
            const long long* ei = (const long long*)edge;
            src = (int)ei[e];
            dst = (int)ei[E + e];
        } else {
            const int* ei = (const int*)edge;
            src = ei[e];
            dst = ei[E + e];
        }
        float4 v = __ldg(&feat[(size_t)src * 16 + lane16]);
        float* p = agg + (size_t)dst * 64 + lane16 * 4;
        asm volatile("red.global.add.v4.f32 [%0], {%1,%2,%3,%4};"
                     :: "l"(p), "f"(v.x), "f"(v.y), "f"(v.z), "f"(v.w)
                     : "memory");
        if (phase1 && lane16 == 0) atomicAdd(&g_deg[dst], 1.0f);
    }
}

// ---------------------------------------------------------------------------
// h1 = relu( [x | agg1/deg] @ [Wr1^T ; Wl1^T] + b1 )   -- K=128 fused GEMM.
// Block: 256 thr, W in smem (32KB), input tile [24 x 128] in smem.
// Each warp -> 3 nodes, each lane -> output channels (lane, lane+32).
// ---------------------------------------------------------------------------
__global__ void k_h1(const float4* __restrict__ x4,
                     const float* __restrict__ Wl1,
                     const float* __restrict__ Wr1,
                     const float* __restrict__ b1) {
    __shared__ float Ws[128 * 64];                 // Ws[k][c]
    __shared__ __align__(16) float In[TILE][128];
    __shared__ float bs[64];

    int tid = threadIdx.x;
    for (int i = tid; i < 64 * 64; i += 256) {
        int c = i >> 6, k = i & 63;
        Ws[k * 64 + c]        = Wr1[c * 64 + k];   // k < 64  : x part
        Ws[(k + 64) * 64 + c] = Wl1[c * 64 + k];   // k >= 64 : agg part
    }
    if (tid < 64) bs[tid] = b1[tid];
    __syncthreads();

    int warp = tid >> 5, lane = tid & 31;
    int ntiles = (N_NODES + TILE - 1) / TILE;

    for (int t = blockIdx.x; t < ntiles; t += gridDim.x) {
        int base = t * TILE;
        int ntile = min(TILE, N_NODES - base);

        for (int i = tid; i < ntile * 16; i += 256) {
            int r = i >> 4, c4 = i & 15;
            size_t n = (size_t)(base + r);
            float4 v = x4[n * 16 + c4];
            *((float4*)&In[r][c4 * 4]) = v;
        }
        for (int i = tid; i < ntile * 16; i += 256) {
            int r = i >> 4, c4 = i & 15;
            size_t n = (size_t)(base + r);
            float inv = 1.0f / fmaxf(g_deg[n], 1.0f);
            float4 v = *((const float4*)&g_agg1[n * 64 + c4 * 4]);
            v.x *= inv; v.y *= inv; v.z *= inv; v.w *= inv;
            *((float4*)&In[r][64 + c4 * 4]) = v;
        }
        __syncthreads();

        float acc[3][2];
        #pragma unroll
        for (int j = 0; j < 3; j++) { acc[j][0] = 0.f; acc[j][1] = 0.f; }

        #pragma unroll 4
        for (int k = 0; k < 128; k++) {
            float w0 = Ws[k * 64 + lane];
            float w1 = Ws[k * 64 + lane + 32];
            #pragma unroll
            for (int j = 0; j < 3; j++) {
                float v = In[warp * 3 + j][k];
                acc[j][0] += v * w0;
                acc[j][1] += v * w1;
            }
        }

        #pragma unroll
        for (int j = 0; j < 3; j++) {
            int r = warp * 3 + j;
            if (r < ntile) {
                size_t n = (size_t)(base + r);
                g_h1[n * 64 + lane]      = fmaxf(acc[j][0] + bs[lane], 0.f);
                g_h1[n * 64 + lane + 32] = fmaxf(acc[j][1] + bs[lane + 32], 0.f);
            }
        }
        __syncthreads();
    }
}

// ---------------------------------------------------------------------------
// Pooling: batch is sorted, so accumulate in registers and flush (atomic)
// only on graph change. 128 threads: ch<64 -> h1, ch>=64 -> agg2/deg.
// ---------------------------------------------------------------------------
__global__ void k_pool(const void* __restrict__ batch) {
    int tid = threadIdx.x;  // 0..127
    const bool is64 = (g_is64 != 0);
    int per = (N_NODES + gridDim.x - 1) / gridDim.x;
    int start = blockIdx.x * per;
    int end = min(start + per, N_NODES);
    if (start >= end) return;

    float acc = 0.f, ccnt = 0.f;
    int cur = -1;
    for (int n = start; n < end; n++) {
        int g = is64 ? (int)((const long long*)batch)[n]
                     : ((const int*)batch)[n];
        if (g != cur) {
            if (cur >= 0) {
                atomicAdd(&g_pooled[cur * 128 + tid], acc);
                if (tid == 0) atomicAdd(&g_cnt[cur], ccnt);
            }
            cur = g; acc = 0.f; ccnt = 0.f;
        }
        size_t nn = (size_t)n;
        float v;
        if (tid < 64) {
            v = g_h1[nn * 64 + tid];
        } else {
            v = g_agg2[nn * 64 + (tid - 64)] * (1.0f / fmaxf(g_deg[n], 1.0f));
        }
        acc += v;
        ccnt += 1.f;
    }
    atomicAdd(&g_pooled[cur * 128 + tid], acc);
    if (tid == 0) atomicAdd(&g_cnt[cur], ccnt);
}

// ---------------------------------------------------------------------------
// out[g][c] = b2[c]*[cnt>0] + sum_k P_h1[g][k]/cnt * Wr2[c][k]
//                           + sum_k P_ag[g][k]/cnt * Wl2[c][k]
// ---------------------------------------------------------------------------
__global__ void k_out(const float* __restrict__ Wl2,
                      const float* __restrict__ Wr2,
                      const float* __restrict__ b2,
                      float* __restrict__ out) {
    int g = blockIdx.x;   // 128
    int c = threadIdx.x;  // 128
    __shared__ float P[128];
    float cntg = g_cnt[g];
    float inv = 1.0f / fmaxf(cntg, 1.0f);
    P[c] = g_pooled[g * 128 + c] * inv;
    __syncthreads();

    float acc = (cntg > 0.f) ? b2[c] : 0.f;
    #pragma unroll 8
    for (int k = 0; k < 64; k++) acc += P[k] * Wr2[c * 64 + k];
    #pragma unroll 8
    for (int k = 0; k < 64; k++) acc += P[64 + k] * Wl2[c * 64 + k];
    out[g * 128 + c] = acc;
}

// ---------------------------------------------------------------------------
extern "C" void kernel_launch(void* const* d_in, const int* in_sizes, int n_in,
                              void* d_out, int out_size) {
    const float* x   = (const float*)d_in[0];
    const void*  edge  = d_in[1];
    const void*  batch = d_in[2];
    const float* Wl1 = (const float*)d_in[3];
    const float* Wr1 = (const float*)d_in[4];
    const float* b1  = (const float*)d_in[5];
    const float* Wl2 = (const float*)d_in[6];
    const float* Wr2 = (const float*)d_in[7];
    const float* b2  = (const float*)d_in[8];
    float* out = (float*)d_out;

    int E = in_sizes[1] / 2;

    k_zero<<<4096, 256>>>((const int*)edge);
    k_scatter<<<8192, 256>>>((const float4*)x, edge, E, 1);
    k_h1<<<4167, 256>>>((const float4*)x, Wl1, Wr1, b1);
    k_scatter<<<8192, 256>>>((const float4*)x, edge, E, 0);
    k_pool<<<800, 128>>>(batch);
    k_out<<<NGRAPHS, 128>>>(Wl2, Wr2, b2, out);
}

// round 3
// speedup vs baseline: 1.5565x; 1.5565x over previous
#include <cuda_runtime.h>

// ---------------------------------------------------------------------------
// GraphSAGE (2x SAGEConv mean-agg + ReLU + global mean pool), fp32.
//
//   agg1[n] = (1/max(deg[n],1)) * sum_{e:dst=n} x[src[e]]
//   h1[n]   = relu( agg1[n] @ Wl1^T + x[n] @ Wr1^T + b1 )
//   agg2[n] = (1/max(deg[n],1)) * sum_{e:dst=n} h1[src[e]]
//   out[g]  = (mean_n agg2) @ Wl2^T + (mean_n h1) @ Wr2^T + b2*[cnt>0]
// h2 per-node is never materialized (pooling commutes with the linear layer).
// ---------------------------------------------------------------------------

#define N_NODES 100000
#define FDIM    64
#define NGRAPHS 128
#define TILE    24   // nodes per block tile in h1 GEMM (3 per warp, 8 warps)
                     // smem: 32KB (W) + 12KB (In) + 256B (b) = 45.3KB < 48KB

__device__ __align__(16) float g_agg1[(size_t)N_NODES * FDIM];
__device__ __align__(16) float g_h1  [(size_t)N_NODES * FDIM];
__device__ __align__(16) float g_agg2[(size_t)N_NODES * FDIM];
__device__ float g_deg[N_NODES];
__device__ float g_pooled[NGRAPHS * 128];   // [g][0:64]=sum h1, [g][64:128]=sum agg2
__device__ float g_cnt[NGRAPHS];
__device__ int   g_is64;

// ---------------------------------------------------------------------------
// Zero accumulators (float4) + detect index width (int64 vs int32).
// For int64 little-endian node ids (< 2^31), every odd 32-bit word is 0.
// ---------------------------------------------------------------------------
__global__ void k_zero(const int* __restrict__ edge_w) {
    size_t stride = (size_t)gridDim.x * blockDim.x;
    size_t t0 = (size_t)blockIdx.x * blockDim.x + threadIdx.x;
    const float4 z = make_float4(0.f, 0.f, 0.f, 0.f);
    float4* a1 = (float4*)g_agg1;
    float4* a2 = (float4*)g_agg2;
    const size_t n4 = (size_t)N_NODES * FDIM / 4;
    for (size_t i = t0; i < n4; i += stride) { a1[i] = z; a2[i] = z; }
    for (size_t i = t0; i < (size_t)N_NODES; i += stride) g_deg[i] = 0.f;
    for (size_t i = t0; i < (size_t)NGRAPHS * 128; i += stride) g_pooled[i] = 0.f;
    for (size_t i = t0; i < (size_t)NGRAPHS; i += stride) g_cnt[i] = 0.f;

    if (blockIdx.x == 0 && threadIdx.x == 0) {
        int is64 = 1;
        #pragma unroll 1
        for (int i = 1; i < 128; i += 2) {
            if (edge_w[i] != 0) { is64 = 0; break; }
        }
        g_is64 = is64;
    }
}

// ---------------------------------------------------------------------------
// Edge scatter: 16 lanes per edge, one float4 per lane (64 ch), unrolled x4
// for MLP (batch index loads -> batch gathers -> batch REDs).
// phase1: feat = x,   agg = g_agg1, also counts degree.
// phase2: feat = h1,  agg = g_agg2.
// ---------------------------------------------------------------------------
__global__ void k_scatter(const float4* __restrict__ xin,
                          const void* __restrict__ edge, int E, int phase1) {
    const float4* feat = phase1 ? xin : (const float4*)g_h1;
    float* agg = phase1 ? g_agg1 : g_agg2;

    int gtid    = blockIdx.x * blockDim.x + threadIdx.x;
    int lane16  = gtid & 15;
    int group   = gtid >> 4;
    int ngroups = (gridDim.x * blockDim.x) >> 4;
    const bool is64 = (g_is64 != 0);
    const long long* ei64 = (const long long*)edge;
    const int*       ei32 = (const int*)edge;

    const int U = 4;
    for (int e0 = group; e0 < E; e0 += U * ngroups) {
        int src[U], dst[U];
        #pragma unroll
        for (int u = 0; u < U; u++) {
            int e = e0 + u * ngroups;
            if (e < E) {
                if (is64) { src[u] = (int)ei64[e]; dst[u] = (int)ei64[E + e]; }
                else      { src[u] = ei32[e];      dst[u] = ei32[E + e]; }
            } else {
                src[u] = -1; dst[u] = 0;
            }
        }
        float4 v[U];
        #pragma unroll
        for (int u = 0; u < U; u++)
            if (src[u] >= 0)
                v[u] = __ldg(&feat[(size_t)src[u] * 16 + lane16]);
        #pragma unroll
        for (int u = 0; u < U; u++) {
            if (src[u] >= 0) {
                float* p = agg + (size_t)dst[u] * 64 + lane16 * 4;
                asm volatile("red.global.add.v4.f32 [%0], {%1,%2,%3,%4};"
                             :: "l"(p), "f"(v[u].x), "f"(v[u].y),
                                "f"(v[u].z), "f"(v[u].w)
                             : "memory");
                if (phase1 && lane16 == 0) atomicAdd(&g_deg[dst[u]], 1.0f);
            }
        }
    }
}

// ---------------------------------------------------------------------------
// h1 = relu( [x | agg1/deg] @ [Wr1^T ; Wl1^T] + b1 )   -- K=128 fused GEMM.
// Persistent blocks: weights loaded into smem ONCE per block, then loop tiles.
// Each warp -> 3 nodes, each lane -> 2 output channels (lane, lane+32).
// ---------------------------------------------------------------------------
__global__ void __launch_bounds__(256) k_h1(const float4* __restrict__ x4,
                     const float* __restrict__ Wl1,
                     const float* __restrict__ Wr1,
                     const float* __restrict__ b1) {
    __shared__ float Ws[128 * 64];                 // Ws[k][c]  (32 KB)
    __shared__ __align__(16) float In[TILE][128];  // 12 KB
    __shared__ float bs[64];

    int tid = threadIdx.x;
    for (int i = tid; i < 64 * 64; i += 256) {
        int c = i >> 6, k = i & 63;
        Ws[k * 64 + c]        = Wr1[c * 64 + k];   // k < 64  : x part
        Ws[(k + 64) * 64 + c] = Wl1[c * 64 + k];   // k >= 64 : agg part
    }
    if (tid < 64) bs[tid] = b1[tid];
    __syncthreads();

    int warp = tid >> 5, lane = tid & 31;
    int ntiles = (N_NODES + TILE - 1) / TILE;

    for (int t = blockIdx.x; t < ntiles; t += gridDim.x) {
        int base = t * TILE;
        int ntile = min(TILE, N_NODES - base);

        for (int i = tid; i < ntile * 16; i += 256) {
            int r = i >> 4, c4 = i & 15;
            size_t n = (size_t)(base + r);
            *((float4*)&In[r][c4 * 4]) = x4[n * 16 + c4];
        }
        for (int i = tid; i < ntile * 16; i += 256) {
            int r = i >> 4, c4 = i & 15;
            size_t n = (size_t)(base + r);
            float inv = 1.0f / fmaxf(g_deg[n], 1.0f);
            float4 v = *((const float4*)&g_agg1[n * 64 + c4 * 4]);
            v.x *= inv; v.y *= inv; v.z *= inv; v.w *= inv;
            *((float4*)&In[r][64 + c4 * 4]) = v;
        }
        __syncthreads();

        float acc[3][2];
        #pragma unroll
        for (int j = 0; j < 3; j++) { acc[j][0] = 0.f; acc[j][1] = 0.f; }

        #pragma unroll 4
        for (int k = 0; k < 128; k++) {
            float w0 = Ws[k * 64 + lane];
            float w1 = Ws[k * 64 + lane + 32];
            #pragma unroll
            for (int j = 0; j < 3; j++) {
                float v = In[warp * 3 + j][k];
                acc[j][0] += v * w0;
                acc[j][1] += v * w1;
            }
        }

        #pragma unroll
        for (int j = 0; j < 3; j++) {
            int r = warp * 3 + j;
            if (r < ntile) {
                size_t n = (size_t)(base + r);
                g_h1[n * 64 + lane]      = fmaxf(acc[j][0] + bs[lane], 0.f);
                g_h1[n * 64 + lane + 32] = fmaxf(acc[j][1] + bs[lane + 32], 0.f);
            }
        }
        __syncthreads();
    }
}

// ---------------------------------------------------------------------------
// Pooling: batch is sorted -> accumulate in registers, atomic-flush on graph
// change. One WARP per node range: lanes 0-15 -> h1 float4s, 16-31 -> agg2
// float4s (scaled by 1/deg).
// ---------------------------------------------------------------------------
#define POOL_BLOCKS 1024
__global__ void k_pool(const void* __restrict__ batch) {
    const int NW = POOL_BLOCKS * 4;
    int w = blockIdx.x * 4 + (threadIdx.x >> 5);
    int lane = threadIdx.x & 31;
    const bool is64 = (g_is64 != 0);
    const long long* b64 = (const long long*)batch;
    const int*       b32 = (const int*)batch;

    int per = (N_NODES + NW - 1) / NW;
    int start = w * per;
    int end = min(start + per, N_NODES);
    if (start >= end) return;

    const bool isH = lane < 16;
    const int c4 = isH ? lane : (lane - 16);

    float4 acc = make_float4(0.f, 0.f, 0.f, 0.f);
    float ccnt = 0.f;
    int cur = -1;

    for (int n = start; n < end; n++) {
        int g = is64 ? (int)b64[n] : b32[n];
        if (g != cur) {
            if (cur >= 0) {
                float* p = g_pooled + cur * 128 + (isH ? 0 : 64) + c4 * 4;
                atomicAdd(p + 0, acc.x); atomicAdd(p + 1, acc.y);
                atomicAdd(p + 2, acc.z); atomicAdd(p + 3, acc.w);
                if (lane == 0) atomicAdd(&g_cnt[cur], ccnt);
            }
            cur = g;
            acc = make_float4(0.f, 0.f, 0.f, 0.f);
            ccnt = 0.f;
        }
        size_t nn = (size_t)n;
        float4 v;
        if (isH) {
            v = *((const float4*)&g_h1[nn * 64 + c4 * 4]);
        } else {
            float inv = 1.0f / fmaxf(g_deg[n], 1.0f);
            v = *((const float4*)&g_agg2[nn * 64 + c4 * 4]);
            v.x *= inv; v.y *= inv; v.z *= inv; v.w *= inv;
        }
        acc.x += v.x; acc.y += v.y; acc.z += v.z; acc.w += v.w;
        ccnt += 1.f;
    }
    float* p = g_pooled + cur * 128 + (isH ? 0 : 64) + c4 * 4;
    atomicAdd(p + 0, acc.x); atomicAdd(p + 1, acc.y);
    atomicAdd(p + 2, acc.z); atomicAdd(p + 3, acc.w);
    if (lane == 0) atomicAdd(&g_cnt[cur], ccnt);
}

// ---------------------------------------------------------------------------
// out[g][c] = b2[c]*[cnt>0] + (P_h1[g]/cnt) . Wr2[c] + (P_ag[g]/cnt) . Wl2[c]
// ---------------------------------------------------------------------------
__global__ void k_out(const float* __restrict__ Wl2,
                      const float* __restrict__ Wr2,
                      const float* __restrict__ b2,
                      float* __restrict__ out) {
    int g = blockIdx.x;   // 128
    int c = threadIdx.x;  // 128
    __shared__ float P[128];
    float cntg = g_cnt[g];
    float inv = 1.0f / fmaxf(cntg, 1.0f);
    P[c] = g_pooled[g * 128 + c] * inv;
    __syncthreads();

    float acc = (cntg > 0.f) ? b2[c] : 0.f;
    #pragma unroll 8
    for (int k = 0; k < 64; k++) acc += P[k] * Wr2[c * 64 + k];
    #pragma unroll 8
    for (int k = 0; k < 64; k++) acc += P[64 + k] * Wl2[c * 64 + k];
    out[g * 128 + c] = acc;
}

// ---------------------------------------------------------------------------
extern "C" void kernel_launch(void* const* d_in, const int* in_sizes, int n_in,
                              void* d_out, int out_size) {
    const float* x   = (const float*)d_in[0];
    const void*  edge  = d_in[1];
    const void*  batch = d_in[2];
    const float* Wl1 = (const float*)d_in[3];
    const float* Wr1 = (const float*)d_in[4];
    const float* b1  = (const float*)d_in[5];
    const float* Wl2 = (const float*)d_in[6];
    const float* Wr2 = (const float*)d_in[7];
    const float* b2  = (const float*)d_in[8];
    float* out = (float*)d_out;

    int E = in_sizes[1] / 2;

    k_zero<<<2048, 256>>>((const int*)edge);
    k_scatter<<<8192, 256>>>((const float4*)x, edge, E, 1);
    k_h1<<<592, 256>>>((const float4*)x, Wl1, Wr1, b1);
    k_scatter<<<8192, 256>>>((const float4*)x, edge, E, 0);
    k_pool<<<POOL_BLOCKS, 128>>>(batch);
    k_out<<<NGRAPHS, 128>>>(Wl2, Wr2, b2, out);
}

// round 5
// speedup vs baseline: 1.9670x; 1.2637x over previous
#include <cuda_runtime.h>
#include <cuda_fp16.h>

// ---------------------------------------------------------------------------
// GraphSAGE (2x SAGEConv mean-agg + ReLU + global mean pool).
// Scatter/aggregate path in f16 (red.global.add.noftz.v4.f16x2),
// GEMMs + self-term + pooling accumulation in fp32.
//
//   agg1[n] = (1/max(deg,1)) * sum_{e:dst=n} x16[src[e]]        (f16 atomics)
//   h1[n]   = relu( agg1 @ Wl1^T + x @ Wr1^T + b1 )             (fp32 GEMM)
//   agg2[n] = (1/max(deg,1)) * sum_{e:dst=n} h1_16[src[e]]      (f16 atomics)
//   out[g]  = (mean agg2) @ Wl2^T + (mean h1) @ Wr2^T + b2*[cnt>0]
// h2 per-node is never materialized (pooling commutes with the linear layer).
// ---------------------------------------------------------------------------

#define N_NODES 100000
#define FDIM    64
#define NGRAPHS 128
#define TILE    24   // smem: 32KB (W) + 12KB (In) + 256B (b) = 45.3KB < 48KB

__device__ __forceinline__ unsigned int h2_as_u(__half2 h) {
    return *reinterpret_cast<unsigned int*>(&h);
}
__device__ __forceinline__ __half2 u_as_h2(unsigned int u) {
    return *reinterpret_cast<__half2*>(&u);
}

__device__ __align__(16) __half g_x16 [(size_t)N_NODES * FDIM];
__device__ __align__(16) __half g_agg1[(size_t)N_NODES * FDIM];
__device__ __align__(16) __half g_h1  [(size_t)N_NODES * FDIM];
__device__ __align__(16) __half g_agg2[(size_t)N_NODES * FDIM];
__device__ float g_deg[N_NODES];
__device__ float g_pooled[NGRAPHS * 128];   // [g][0:64]=sum h1, [g][64:128]=sum agg2
__device__ float g_cnt[NGRAPHS];
__device__ int   g_is64;

// ---------------------------------------------------------------------------
// Zero accumulators, convert x -> f16, detect index width (int64 vs int32).
// For int64 little-endian node ids (< 2^31), every odd 32-bit word is 0.
// ---------------------------------------------------------------------------
__global__ void k_zero(const float4* __restrict__ x4,
                       const int* __restrict__ edge_w) {
    size_t stride = (size_t)gridDim.x * blockDim.x;
    size_t t0 = (size_t)blockIdx.x * blockDim.x + threadIdx.x;
    const uint4 z4 = make_uint4(0u, 0u, 0u, 0u);
    uint4* a1 = (uint4*)g_agg1;
    uint4* a2 = (uint4*)g_agg2;
    uint4* xh = (uint4*)g_x16;
    const size_t n16 = (size_t)N_NODES * FDIM / 8;   // uint4 = 8 halves

    for (size_t i = t0; i < n16; i += stride) {
        a1[i] = z4;
        a2[i] = z4;
        // convert 8 floats -> 8 halves
        float4 a = x4[2 * i];
        float4 b = x4[2 * i + 1];
        uint4 o;
        o.x = h2_as_u(__floats2half2_rn(a.x, a.y));
        o.y = h2_as_u(__floats2half2_rn(a.z, a.w));
        o.z = h2_as_u(__floats2half2_rn(b.x, b.y));
        o.w = h2_as_u(__floats2half2_rn(b.z, b.w));
        xh[i] = o;
    }
    for (size_t i = t0; i < (size_t)N_NODES; i += stride) g_deg[i] = 0.f;
    for (size_t i = t0; i < (size_t)NGRAPHS * 128; i += stride) g_pooled[i] = 0.f;
    for (size_t i = t0; i < (size_t)NGRAPHS; i += stride) g_cnt[i] = 0.f;

    if (blockIdx.x == 0 && threadIdx.x == 0) {
        int is64 = 1;
        #pragma unroll 1
        for (int i = 1; i < 128; i += 2) {
            if (edge_w[i] != 0) { is64 = 0; break; }
        }
        g_is64 = is64;
    }
}

// ---------------------------------------------------------------------------
// Edge scatter (f16): 8 lanes per edge, one uint4 (8 halves) per lane.
// red.global.add.noftz.v4.f16x2 -> 64 channels in 8 lane-ops.
// phase1: feat = x16, agg = g_agg1, also counts degree.
// phase2: feat = h1,  agg = g_agg2.
// ---------------------------------------------------------------------------
__global__ void k_scatter(const void* __restrict__ edge, int E, int phase1) {
    const uint4* feat = phase1 ? (const uint4*)g_x16 : (const uint4*)g_h1;
    __half* agg = phase1 ? g_agg1 : g_agg2;

    int gtid    = blockIdx.x * blockDim.x + threadIdx.x;
    int lane8   = gtid & 7;
    int group   = gtid >> 3;
    int ngroups = (gridDim.x * blockDim.x) >> 3;
    const bool is64 = (g_is64 != 0);
    const long long* ei64 = (const long long*)edge;
    const int*       ei32 = (const int*)edge;

    const int U = 4;
    for (int e0 = group; e0 < E; e0 += U * ngroups) {
        int src[U], dst[U];
        #pragma unroll
        for (int u = 0; u < U; u++) {
            int e = e0 + u * ngroups;
            if (e < E) {
                if (is64) { src[u] = (int)ei64[e]; dst[u] = (int)ei64[E + e]; }
                else      { src[u] = ei32[e];      dst[u] = ei32[E + e]; }
            } else {
                src[u] = -1; dst[u] = 0;
            }
        }
        uint4 v[U];
        #pragma unroll
        for (int u = 0; u < U; u++)
            if (src[u] >= 0)
                v[u] = __ldg(&feat[(size_t)src[u] * 8 + lane8]);
        #pragma unroll
        for (int u = 0; u < U; u++) {
            if (src[u] >= 0) {
                __half* p = agg + (size_t)dst[u] * 64 + lane8 * 8;
                asm volatile("red.global.add.noftz.v4.f16x2 [%0], {%1,%2,%3,%4};"
                             :: "l"(p), "r"(v[u].x), "r"(v[u].y),
                                "r"(v[u].z), "r"(v[u].w)
                             : "memory");
                if (phase1 && lane8 == 0) atomicAdd(&g_deg[dst[u]], 1.0f);
            }
        }
    }
}

// ---------------------------------------------------------------------------
// h1 = relu( [x | agg1/deg] @ [Wr1^T ; Wl1^T] + b1 )   -- K=128 fused GEMM.
// Persistent blocks: weights in smem once per block. x self-term read fp32,
// agg1 read f16 (+1/deg scale), accumulate fp32, store h1 as packed half2.
// Each warp -> 3 nodes, each lane -> channels (2*lane, 2*lane+1).
// ---------------------------------------------------------------------------
__global__ void __launch_bounds__(256) k_h1(const float4* __restrict__ x4,
                     const float* __restrict__ Wl1,
                     const float* __restrict__ Wr1,
                     const float* __restrict__ b1) {
    __shared__ float Ws[128 * 64];                 // Ws[k][c]  (32 KB)
    __shared__ __align__(16) float In[TILE][128];  // 12 KB
    __shared__ float bs[64];

    int tid = threadIdx.x;
    for (int i = tid; i < 64 * 64; i += 256) {
        int c = i >> 6, k = i & 63;
        Ws[k * 64 + c]        = Wr1[c * 64 + k];   // k < 64  : x part
        Ws[(k + 64) * 64 + c] = Wl1[c * 64 + k];   // k >= 64 : agg part
    }
    if (tid < 64) bs[tid] = b1[tid];
    __syncthreads();

    int warp = tid >> 5, lane = tid & 31;
    int ntiles = (N_NODES + TILE - 1) / TILE;

    for (int t = blockIdx.x; t < ntiles; t += gridDim.x) {
        int base = t * TILE;
        int ntile = min(TILE, N_NODES - base);

        // x part (fp32)
        for (int i = tid; i < ntile * 16; i += 256) {
            int r = i >> 4, c4 = i & 15;
            size_t n = (size_t)(base + r);
            *((float4*)&In[r][c4 * 4]) = x4[n * 16 + c4];
        }
        // agg part (f16 -> fp32, scaled by 1/deg)
        for (int i = tid; i < ntile * 8; i += 256) {
            int r = i >> 3, c8 = i & 7;
            size_t n = (size_t)(base + r);
            float inv = 1.0f / fmaxf(g_deg[n], 1.0f);
            uint4 raw = *((const uint4*)(g_agg1 + n * 64) + c8);
            float2 f0 = __half22float2(u_as_h2(raw.x));
            float2 f1 = __half22float2(u_as_h2(raw.y));
            float2 f2 = __half22float2(u_as_h2(raw.z));
            float2 f3 = __half22float2(u_as_h2(raw.w));
            float* d = &In[r][64 + c8 * 8];
            d[0] = f0.x * inv; d[1] = f0.y * inv;
            d[2] = f1.x * inv; d[3] = f1.y * inv;
            d[4] = f2.x * inv; d[5] = f2.y * inv;
            d[6] = f3.x * inv; d[7] = f3.y * inv;
        }
        __syncthreads();

        float acc[3][2];
        #pragma unroll
        for (int j = 0; j < 3; j++) { acc[j][0] = 0.f; acc[j][1] = 0.f; }

        #pragma unroll 4
        for (int k = 0; k < 128; k++) {
            float2 w = *((const float2*)&Ws[k * 64 + 2 * lane]);
            #pragma unroll
            for (int j = 0; j < 3; j++) {
                float v = In[warp * 3 + j][k];
                acc[j][0] += v * w.x;
                acc[j][1] += v * w.y;
            }
        }

        float b0 = bs[2 * lane], b1v = bs[2 * lane + 1];
        #pragma unroll
        for (int j = 0; j < 3; j++) {
            int r = warp * 3 + j;
            if (r < ntile) {
                size_t n = (size_t)(base + r);
                float o0 = fmaxf(acc[j][0] + b0, 0.f);
                float o1 = fmaxf(acc[j][1] + b1v, 0.f);
                *((__half2*)(g_h1 + n * 64 + 2 * lane)) = __floats2half2_rn(o0, o1);
            }
        }
        __syncthreads();
    }
}

// ---------------------------------------------------------------------------
// Pooling: batch is sorted -> accumulate in fp32 registers, atomic-flush on
// graph change. One WARP per node range: lanes 0-15 -> h1 (f16), lanes
// 16-31 -> agg2 (f16, scaled by 1/deg). Each lane: 4 channels (uint2 load).
// ---------------------------------------------------------------------------
#define POOL_BLOCKS 1024
__global__ void k_pool(const void* __restrict__ batch) {
    const int NW = POOL_BLOCKS * 4;
    int w = blockIdx.x * 4 + (threadIdx.x >> 5);
    int lane = threadIdx.x & 31;
    const bool is64 = (g_is64 != 0);
    const long long* b64 = (const long long*)batch;
    const int*       b32 = (const int*)batch;

    int per = (N_NODES + NW - 1) / NW;
    int start = w * per;
    int end = min(start + per, N_NODES);
    if (start >= end) return;

    const bool isH = lane < 16;
    const int c4 = isH ? lane : (lane - 16);
    const __half* srcbuf = isH ? g_h1 : g_agg2;

    float4 acc = make_float4(0.f, 0.f, 0.f, 0.f);
    float ccnt = 0.f;
    int cur = -1;

    for (int n = start; n < end; n++) {
        int g = is64 ? (int)b64[n] : b32[n];
        if (g != cur) {
            if (cur >= 0) {
                float* p = g_pooled + cur * 128 + (isH ? 0 : 64) + c4 * 4;
                atomicAdd(p + 0, acc.x); atomicAdd(p + 1, acc.y);
                atomicAdd(p + 2, acc.z); atomicAdd(p + 3, acc.w);
                if (lane == 0) atomicAdd(&g_cnt[cur], ccnt);
            }
            cur = g;
            acc = make_float4(0.f, 0.f, 0.f, 0.f);
            ccnt = 0.f;
        }
        size_t nn = (size_t)n;
        uint2 raw = *((const uint2*)(srcbuf + nn * 64 + c4 * 4));
        float2 f0 = __half22float2(u_as_h2(raw.x));
        float2 f1 = __half22float2(u_as_h2(raw.y));
        float s = isH ? 1.0f : (1.0f / fmaxf(g_deg[n], 1.0f));
        acc.x += f0.x * s; acc.y += f0.y * s;
        acc.z += f1.x * s; acc.w += f1.y * s;
        ccnt += 1.f;
    }
    float* p = g_pooled + cur * 128 + (isH ? 0 : 64) + c4 * 4;
    atomicAdd(p + 0, acc.x); atomicAdd(p + 1, acc.y);
    atomicAdd(p + 2, acc.z); atomicAdd(p + 3, acc.w);
    if (lane == 0) atomicAdd(&g_cnt[cur], ccnt);
}

// ---------------------------------------------------------------------------
// out[g][c] = b2[c]*[cnt>0] + (P_h1[g]/cnt) . Wr2[c] + (P_ag[g]/cnt) . Wl2[c]
// ---------------------------------------------------------------------------
__global__ void k_out(const float* __restrict__ Wl2,
                      const float* __restrict__ Wr2,
                      const float* __restrict__ b2,
                      float* __restrict__ out) {
    int g = blockIdx.x;   // 128
    int c = threadIdx.x;  // 128
    __shared__ float P[128];
    float cntg = g_cnt[g];
    float inv = 1.0f / fmaxf(cntg, 1.0f);
    P[c] = g_pooled[g * 128 + c] * inv;
    __syncthreads();

    float acc = (cntg > 0.f) ? b2[c] : 0.f;
    #pragma unroll 8
    for (int k = 0; k < 64; k++) acc += P[k] * Wr2[c * 64 + k];
    #pragma unroll 8
    for (int k = 0; k < 64; k++) acc += P[64 + k] * Wl2[c * 64 + k];
    out[g * 128 + c] = acc;
}

// ---------------------------------------------------------------------------
extern "C" void kernel_launch(void* const* d_in, const int* in_sizes, int n_in,
                              void* d_out, int out_size) {
    const float* x   = (const float*)d_in[0];
    const void*  edge  = d_in[1];
    const void*  batch = d_in[2];
    const float* Wl1 = (const float*)d_in[3];
    const float* Wr1 = (const float*)d_in[4];
    const float* b1  = (const float*)d_in[5];
    const float* Wl2 = (const float*)d_in[6];
    const float* Wr2 = (const float*)d_in[7];
    const float* b2  = (const float*)d_in[8];
    float* out = (float*)d_out;

    int E = in_sizes[1] / 2;

    k_zero<<<2048, 256>>>((const float4*)x, (const int*)edge);
    k_scatter<<<8192, 256>>>(edge, E, 1);
    k_h1<<<592, 256>>>((const float4*)x, Wl1, Wr1, b1);
    k_scatter<<<8192, 256>>>(edge, E, 0);
    k_pool<<<POOL_BLOCKS, 128>>>(batch);
    k_out<<<NGRAPHS, 128>>>(Wl2, Wr2, b2, out);
}

// round 6
// speedup vs baseline: 2.9833x; 1.5167x over previous
#include <cuda_runtime.h>
#include <cuda_fp16.h>

// ---------------------------------------------------------------------------
// GraphSAGE (2x SAGEConv mean-agg + ReLU + global mean pool).
// Scatter/aggregate in f16 (red.global.add.noftz.v4.f16x2).
// h1 layer on tensor cores (mma.sync m16n8k16, f16 in / fp32 accum).
// Pooling + final projection fp32.
// ---------------------------------------------------------------------------

#define N_NODES 100000
#define FDIM    64
#define NGRAPHS 128

__device__ __forceinline__ unsigned int h2_as_u(__half2 h) {
    return *reinterpret_cast<unsigned int*>(&h);
}
__device__ __forceinline__ __half2 u_as_h2(unsigned int u) {
    return *reinterpret_cast<__half2*>(&u);
}

__device__ __align__(16) __half g_x16 [(size_t)N_NODES * FDIM];
__device__ __align__(16) __half g_agg1[(size_t)N_NODES * FDIM];
__device__ __align__(16) __half g_h1  [(size_t)N_NODES * FDIM];
__device__ __align__(16) __half g_agg2[(size_t)N_NODES * FDIM];
__device__ float g_deg[N_NODES];
__device__ float g_pooled[NGRAPHS * 128];   // [g][0:64]=sum h1, [g][64:128]=sum agg2
__device__ float g_cnt[NGRAPHS];
__device__ int   g_is64;

// ---------------------------------------------------------------------------
// Zero accumulators, convert x -> f16, detect index width (int64 vs int32).
// ---------------------------------------------------------------------------
__global__ void k_zero(const float4* __restrict__ x4,
                       const int* __restrict__ edge_w) {
    size_t stride = (size_t)gridDim.x * blockDim.x;
    size_t t0 = (size_t)blockIdx.x * blockDim.x + threadIdx.x;
    const uint4 z4 = make_uint4(0u, 0u, 0u, 0u);
    uint4* a1 = (uint4*)g_agg1;
    uint4* a2 = (uint4*)g_agg2;
    uint4* xh = (uint4*)g_x16;
    const size_t n16 = (size_t)N_NODES * FDIM / 8;   // uint4 = 8 halves

    for (size_t i = t0; i < n16; i += stride) {
        a1[i] = z4;
        a2[i] = z4;
        float4 a = x4[2 * i];
        float4 b = x4[2 * i + 1];
        uint4 o;
        o.x = h2_as_u(__floats2half2_rn(a.x, a.y));
        o.y = h2_as_u(__floats2half2_rn(a.z, a.w));
        o.z = h2_as_u(__floats2half2_rn(b.x, b.y));
        o.w = h2_as_u(__floats2half2_rn(b.z, b.w));
        xh[i] = o;
    }
    for (size_t i = t0; i < (size_t)N_NODES; i += stride) g_deg[i] = 0.f;
    for (size_t i = t0; i < (size_t)NGRAPHS * 128; i += stride) g_pooled[i] = 0.f;
    for (size_t i = t0; i < (size_t)NGRAPHS; i += stride) g_cnt[i] = 0.f;

    if (blockIdx.x == 0 && threadIdx.x == 0) {
        int is64 = 1;
        #pragma unroll 1
        for (int i = 1; i < 128; i += 2) {
            if (edge_w[i] != 0) { is64 = 0; break; }
        }
        g_is64 = is64;
    }
}

// ---------------------------------------------------------------------------
// Edge scatter (f16): 8 lanes per edge, one uint4 (8 halves) per lane.
// ---------------------------------------------------------------------------
__global__ void k_scatter(const void* __restrict__ edge, int E, int phase1) {
    const uint4* feat = phase1 ? (const uint4*)g_x16 : (const uint4*)g_h1;
    __half* agg = phase1 ? g_agg1 : g_agg2;

    int gtid    = blockIdx.x * blockDim.x + threadIdx.x;
    int lane8   = gtid & 7;
    int group   = gtid >> 3;
    int ngroups = (gridDim.x * blockDim.x) >> 3;
    const bool is64 = (g_is64 != 0);
    const long long* ei64 = (const long long*)edge;
    const int*       ei32 = (const int*)edge;

    const int U = 4;
    for (int e0 = group; e0 < E; e0 += U * ngroups) {
        int src[U], dst[U];
        #pragma unroll
        for (int u = 0; u < U; u++) {
            int e = e0 + u * ngroups;
            if (e < E) {
                if (is64) { src[u] = (int)ei64[e]; dst[u] = (int)ei64[E + e]; }
                else      { src[u] = ei32[e];      dst[u] = ei32[E + e]; }
            } else {
                src[u] = -1; dst[u] = 0;
            }
        }
        uint4 v[U];
        #pragma unroll
        for (int u = 0; u < U; u++)
            if (src[u] >= 0)
                v[u] = __ldg(&feat[(size_t)src[u] * 8 + lane8]);
        #pragma unroll
        for (int u = 0; u < U; u++) {
            if (src[u] >= 0) {
                __half* p = agg + (size_t)dst[u] * 64 + lane8 * 8;
                asm volatile("red.global.add.noftz.v4.f16x2 [%0], {%1,%2,%3,%4};"
                             :: "l"(p), "r"(v[u].x), "r"(v[u].y),
                                "r"(v[u].z), "r"(v[u].w)
                             : "memory");
                if (phase1 && lane8 == 0) atomicAdd(&g_deg[dst[u]], 1.0f);
            }
        }
    }
}

// ---------------------------------------------------------------------------
// h1 = relu( [x16 | agg1/deg] @ Wc^T + b1 ) on tensor cores.
// Wc = [Wr1 ; Wl1] as f16, stored transposed in smem: Wt[c][k], stride 136
// halves (pad 8 => LDS bank pattern 4g+t, conflict-free).
// Each warp owns one 16-node tile; A fragments loaded straight from global
// (g_x16 / g_agg1, the latter scaled by 1/deg in registers).
// mma.sync.m16n8k16: A row-major 16x16 f16, B col-major 16x8 f16, D fp32.
// ---------------------------------------------------------------------------
__device__ __forceinline__ void mma16816(
    float& d0, float& d1, float& d2, float& d3,
    unsigned a0, unsigned a1, unsigned a2, unsigned a3,
    unsigned b0, unsigned b1)
{
    asm volatile(
        "mma.sync.aligned.m16n8k16.row.col.f32.f16.f16.f32 "
        "{%0,%1,%2,%3}, {%4,%5,%6,%7}, {%8,%9}, {%0,%1,%2,%3};"
        : "+f"(d0), "+f"(d1), "+f"(d2), "+f"(d3)
        : "r"(a0), "r"(a1), "r"(a2), "r"(a3), "r"(b0), "r"(b1));
}

__device__ __forceinline__ unsigned scale_h2(unsigned u, float s) {
    float2 f = __half22float2(u_as_h2(u));
    return h2_as_u(__floats2half2_rn(f.x * s, f.y * s));
}

#define WT_STRIDE 136
#define NTILES (N_NODES / 16)   // 6250, exact

__global__ void __launch_bounds__(256) k_h1(const float* __restrict__ Wl1,
                                            const float* __restrict__ Wr1,
                                            const float* __restrict__ b1) {
    __shared__ __half Wt[64 * WT_STRIDE];  // Wt[c][k], k<64: Wr1, k>=64: Wl1
    __shared__ float bsm[64];

    int tid = threadIdx.x;
    for (int i = tid; i < 64 * 128; i += 256) {
        int c = i >> 7, k = i & 127;
        float v = (k < 64) ? Wr1[c * 64 + k] : Wl1[c * 64 + (k - 64)];
        Wt[c * WT_STRIDE + k] = __float2half(v);
    }
    if (tid < 64) bsm[tid] = b1[tid];
    __syncthreads();

    int lane = tid & 31;
    int g = lane >> 2;        // 0..7
    int t = lane & 3;         // 0..3
    int warp_g = blockIdx.x * 8 + (tid >> 5);
    int nwarps = gridDim.x * 8;

    for (int tile = warp_g; tile < NTILES; tile += nwarps) {
        int nb = tile * 16;
        size_t n0 = (size_t)(nb + g);
        size_t n1 = n0 + 8;
        float inv0 = 1.0f / fmaxf(g_deg[n0], 1.0f);
        float inv1 = 1.0f / fmaxf(g_deg[n1], 1.0f);

        float acc[8][4];
        #pragma unroll
        for (int j = 0; j < 8; j++)
            #pragma unroll
            for (int q = 0; q < 4; q++) acc[j][q] = 0.f;

        #pragma unroll
        for (int kk = 0; kk < 8; kk++) {
            unsigned a0, a1, a2, a3;
            if (kk < 4) {
                const __half* base = g_x16;
                int kb = kk * 16;
                a0 = *(const unsigned*)(base + n0 * 64 + kb + 2 * t);
                a1 = *(const unsigned*)(base + n1 * 64 + kb + 2 * t);
                a2 = *(const unsigned*)(base + n0 * 64 + kb + 8 + 2 * t);
                a3 = *(const unsigned*)(base + n1 * 64 + kb + 8 + 2 * t);
            } else {
                const __half* base = g_agg1;
                int kb = (kk - 4) * 16;
                a0 = scale_h2(*(const unsigned*)(base + n0 * 64 + kb + 2 * t), inv0);
                a1 = scale_h2(*(const unsigned*)(base + n1 * 64 + kb + 2 * t), inv1);
                a2 = scale_h2(*(const unsigned*)(base + n0 * 64 + kb + 8 + 2 * t), inv0);
                a3 = scale_h2(*(const unsigned*)(base + n1 * 64 + kb + 8 + 2 * t), inv1);
            }
            int kb = kk * 16;
            #pragma unroll
            for (int j = 0; j < 8; j++) {
                unsigned b0 = *(const unsigned*)&Wt[(j * 8 + g) * WT_STRIDE + kb + 2 * t];
                unsigned b1v = *(const unsigned*)&Wt[(j * 8 + g) * WT_STRIDE + kb + 8 + 2 * t];
                mma16816(acc[j][0], acc[j][1], acc[j][2], acc[j][3],
                         a0, a1, a2, a3, b0, b1v);
            }
        }

        // epilogue: +bias, relu, f16 store. D layout: c0=D[g][2t], c1=D[g][2t+1],
        // c2=D[g+8][2t], c3=D[g+8][2t+1]; cols = j*8 + 2t(+1).
        #pragma unroll
        for (int j = 0; j < 8; j++) {
            int col = j * 8 + 2 * t;
            float bc0 = bsm[col], bc1 = bsm[col + 1];
            float o0 = fmaxf(acc[j][0] + bc0, 0.f);
            float o1 = fmaxf(acc[j][1] + bc1, 0.f);
            float o2 = fmaxf(acc[j][2] + bc0, 0.f);
            float o3 = fmaxf(acc[j][3] + bc1, 0.f);
            *((__half2*)(g_h1 + n0 * 64 + col)) = __floats2half2_rn(o0, o1);
            *((__half2*)(g_h1 + n1 * 64 + col)) = __floats2half2_rn(o2, o3);
        }
    }
}

// ---------------------------------------------------------------------------
// Pooling: batch sorted -> register accumulate, atomic-flush on graph change.
// One WARP per node range: lanes 0-15 -> h1, 16-31 -> agg2 * 1/deg.
// ---------------------------------------------------------------------------
#define POOL_BLOCKS 1024
__global__ void k_pool(const void* __restrict__ batch) {
    const int NW = POOL_BLOCKS * 4;
    int w = blockIdx.x * 4 + (threadIdx.x >> 5);
    int lane = threadIdx.x & 31;
    const bool is64 = (g_is64 != 0);
    const long long* b64 = (const long long*)batch;
    const int*       b32 = (const int*)batch;

    int per = (N_NODES + NW - 1) / NW;
    int start = w * per;
    int end = min(start + per, N_NODES);
    if (start >= end) return;

    const bool isH = lane < 16;
    const int c4 = isH ? lane : (lane - 16);
    const __half* srcbuf = isH ? g_h1 : g_agg2;

    float4 acc = make_float4(0.f, 0.f, 0.f, 0.f);
    float ccnt = 0.f;
    int cur = -1;

    for (int n = start; n < end; n++) {
        int g = is64 ? (int)b64[n] : b32[n];
        if (g != cur) {
            if (cur >= 0) {
                float* p = g_pooled + cur * 128 + (isH ? 0 : 64) + c4 * 4;
                atomicAdd(p + 0, acc.x); atomicAdd(p + 1, acc.y);
                atomicAdd(p + 2, acc.z); atomicAdd(p + 3, acc.w);
                if (lane == 0) atomicAdd(&g_cnt[cur], ccnt);
            }
            cur = g;
            acc = make_float4(0.f, 0.f, 0.f, 0.f);
            ccnt = 0.f;
        }
        size_t nn = (size_t)n;
        uint2 raw = *((const uint2*)(srcbuf + nn * 64 + c4 * 4));
        float2 f0 = __half22float2(u_as_h2(raw.x));
        float2 f1 = __half22float2(u_as_h2(raw.y));
        float s = isH ? 1.0f : (1.0f / fmaxf(g_deg[n], 1.0f));
        acc.x += f0.x * s; acc.y += f0.y * s;
        acc.z += f1.x * s; acc.w += f1.y * s;
        ccnt += 1.f;
    }
    float* p = g_pooled + cur * 128 + (isH ? 0 : 64) + c4 * 4;
    atomicAdd(p + 0, acc.x); atomicAdd(p + 1, acc.y);
    atomicAdd(p + 2, acc.z); atomicAdd(p + 3, acc.w);
    if (lane == 0) atomicAdd(&g_cnt[cur], ccnt);
}

// ---------------------------------------------------------------------------
// out[g][c] = b2[c]*[cnt>0] + (P_h1[g]/cnt) . Wr2[c] + (P_ag[g]/cnt) . Wl2[c]
// ---------------------------------------------------------------------------
__global__ void k_out(const float* __restrict__ Wl2,
                      const float* __restrict__ Wr2,
                      const float* __restrict__ b2,
                      float* __restrict__ out) {
    int g = blockIdx.x;   // 128
    int c = threadIdx.x;  // 128
    __shared__ float P[128];
    float cntg = g_cnt[g];
    float inv = 1.0f / fmaxf(cntg, 1.0f);
    P[c] = g_pooled[g * 128 + c] * inv;
    __syncthreads();

    float acc = (cntg > 0.f) ? b2[c] : 0.f;
    #pragma unroll 8
    for (int k = 0; k < 64; k++) acc += P[k] * Wr2[c * 64 + k];
    #pragma unroll 8
    for (int k = 0; k < 64; k++) acc += P[64 + k] * Wl2[c * 64 + k];
    out[g * 128 + c] = acc;
}

// ---------------------------------------------------------------------------
extern "C" void kernel_launch(void* const* d_in, const int* in_sizes, int n_in,
                              void* d_out, int out_size) {
    const float* x   = (const float*)d_in[0];
    const void*  edge  = d_in[1];
    const void*  batch = d_in[2];
    const float* Wl1 = (const float*)d_in[3];
    const float* Wr1 = (const float*)d_in[4];
    const float* b1  = (const float*)d_in[5];
    const float* Wl2 = (const float*)d_in[6];
    const float* Wr2 = (const float*)d_in[7];
    const float* b2  = (const float*)d_in[8];
    float* out = (float*)d_out;

    int E = in_sizes[1] / 2;

    k_zero<<<2048, 256>>>((const float4*)x, (const int*)edge);
    k_scatter<<<8192, 256>>>(edge, E, 1);
    k_h1<<<296, 256>>>(Wl1, Wr1, b1);
    k_scatter<<<8192, 256>>>(edge, E, 0);
    k_pool<<<POOL_BLOCKS, 128>>>(batch);
    k_out<<<NGRAPHS, 128>>>(Wl2, Wr2, b2, out);
}